// round 16
// baseline (speedup 1.0000x reference)
#include <cuda_runtime.h>
#include <cuda_bf16.h>
#include <cstdint>
#include <math.h>

// Problem constants
#define Bsz 2
#define Ssz 2048
#define Esz 1024
#define Hsz 16
#define Dsz 64
#define TOK (Bsz*Ssz)        // 4096 tokens
#define E3  (3*Esz)          // 3072
#define NKT (Ssz/64)         // 32 key tiles per sequence

// Scratch (static device globals — no allocation)
__device__ float        g_vf  [ (size_t)TOK * Esz ];    // fp32 V output (compact)
__device__ __nv_bfloat16 g_xnh [ (size_t)TOK * Esz ];
__device__ __nv_bfloat16 g_xnl [ (size_t)TOK * Esz ];
__device__ __nv_bfloat16 g_wqh [ (size_t)E3  * Esz ];   // rows 0..2047 = ROTATED qk W, 2048.. = V hi
__device__ __nv_bfloat16 g_wql [ (size_t)E3  * Esz ];   // only V rows used
__device__ __nv_bfloat16 g_woh [ (size_t)Esz * Esz ];
__device__ __nv_bfloat16 g_wol [ (size_t)Esz * Esz ];
__device__ __nv_bfloat16 g_qh  [ (size_t)TOK * Esz ];
__device__ __nv_bfloat16 g_kh  [ (size_t)TOK * Esz ];
__device__ __nv_bfloat16 g_vth [ (size_t)TOK * Esz ];   // [bh][d][S]
__device__ __nv_bfloat16 g_ath [ (size_t)TOK * Esz ];
__device__ __nv_bfloat16 g_atl [ (size_t)TOK * Esz ];
__device__ float g_ts  [ (size_t)Bsz * Hsz * NKT * Dsz ];
__device__ float g_epts[ (size_t)Bsz * Hsz * NKT * Dsz ];
__device__ float g_pvs [ (size_t)Bsz * Hsz * Ssz * Dsz ];
__device__ float g_qb2 [ 2 * Esz ];                     // rotated qk bias
__device__ float g_sin [ Esz ];
__device__ float g_cos [ Esz ];

// ---------------------------------------------------------------------------
// helpers
// ---------------------------------------------------------------------------
__device__ __forceinline__ void mma_bf16(float* d,
                                         uint32_t a0, uint32_t a1, uint32_t a2, uint32_t a3,
                                         uint32_t b0, uint32_t b1)
{
    asm volatile("mma.sync.aligned.m16n8k16.row.col.f32.bf16.bf16.f32 "
        "{%0,%1,%2,%3}, {%4,%5,%6,%7}, {%8,%9}, {%0,%1,%2,%3};"
        : "+f"(d[0]), "+f"(d[1]), "+f"(d[2]), "+f"(d[3])
        : "r"(a0), "r"(a1), "r"(a2), "r"(a3), "r"(b0), "r"(b1));
}

__device__ __forceinline__ void ldsm_x4(uint32_t& r0, uint32_t& r1,
                                        uint32_t& r2, uint32_t& r3,
                                        const void* smem_ptr)
{
    uint32_t addr = (uint32_t)__cvta_generic_to_shared(smem_ptr);
    asm volatile("ldmatrix.sync.aligned.m8n8.x4.shared.b16 {%0,%1,%2,%3}, [%4];"
                 : "=r"(r0), "=r"(r1), "=r"(r2), "=r"(r3) : "r"(addr));
}

__device__ __forceinline__ uint32_t packbf(float lo, float hi)
{
    __nv_bfloat162 t = __floats2bfloat162_rn(lo, hi);
    return *reinterpret_cast<uint32_t*>(&t);
}

__device__ __forceinline__ void split2(float a, float b, uint32_t& hi, uint32_t& lo)
{
    float ha = __bfloat162float(__float2bfloat16_rn(a));
    float hb = __bfloat162float(__float2bfloat16_rn(b));
    hi = packbf(ha, hb);
    lo = packbf(a - ha, b - hb);
}

__device__ __forceinline__ void cp_async16(void* smem_dst, const void* gmem_src)
{
    uint32_t s = (uint32_t)__cvta_generic_to_shared(smem_dst);
    asm volatile("cp.async.cg.shared.global [%0], [%1], 16;" :: "r"(s), "l"(gmem_src));
}
#define CP_COMMIT()  asm volatile("cp.async.commit_group;")
#define CP_WAIT(n)   asm volatile("cp.async.wait_group %0;" :: "n"(n))

// ---------------------------------------------------------------------------
// LayerNorm -> hi/lo bf16 directly. One block per token, 256 threads.
// ---------------------------------------------------------------------------
__global__ void ln_kernel(const float* __restrict__ x,
                          const float* __restrict__ w,
                          const float* __restrict__ b,
                          __nv_bfloat16* __restrict__ oh,
                          __nv_bfloat16* __restrict__ ol)
{
    int t   = blockIdx.x;
    int tid = threadIdx.x;
    const float4* xr = reinterpret_cast<const float4*>(x + (size_t)t * Esz);
    float4 v = xr[tid];

    float s  = v.x + v.y + v.z + v.w;
    float ss = v.x*v.x + v.y*v.y + v.z*v.z + v.w*v.w;
    #pragma unroll
    for (int off = 16; off; off >>= 1) {
        s  += __shfl_xor_sync(0xffffffffu, s,  off);
        ss += __shfl_xor_sync(0xffffffffu, ss, off);
    }
    __shared__ float red[16];
    int wid = tid >> 5;
    if ((tid & 31) == 0) { red[wid] = s; red[8 + wid] = ss; }
    __syncthreads();
    float tot = 0.f, tot2 = 0.f;
    #pragma unroll
    for (int i = 0; i < 8; i++) { tot += red[i]; tot2 += red[8 + i]; }

    float mu   = tot * (1.0f / Esz);
    float var  = tot2 * (1.0f / Esz) - mu * mu;
    float rstd = rsqrtf(var + 1e-5f);

    const float4 wv = reinterpret_cast<const float4*>(w)[tid];
    const float4 bv = reinterpret_cast<const float4*>(b)[tid];
    float o0 = (v.x - mu) * rstd * wv.x + bv.x;
    float o1 = (v.y - mu) * rstd * wv.y + bv.y;
    float o2 = (v.z - mu) * rstd * wv.z + bv.z;
    float o3 = (v.w - mu) * rstd * wv.w + bv.w;

    uint32_t h0, l0, h1, l1;
    split2(o0, o1, h0, l0);
    split2(o2, o3, h1, l1);
    reinterpret_cast<uint2*>(oh + (size_t)t * Esz)[tid] = make_uint2(h0, h1);
    reinterpret_cast<uint2*>(ol + (size_t)t * Esz)[tid] = make_uint2(l0, l1);
}

// ---------------------------------------------------------------------------
// Elementwise fp32 -> hi/lo bf16 split
// ---------------------------------------------------------------------------
__global__ void cvt_split_kernel(const float* __restrict__ src,
                                 __nv_bfloat16* __restrict__ hi,
                                 __nv_bfloat16* __restrict__ lo, int n4)
{
    int i = blockIdx.x * blockDim.x + threadIdx.x;
    if (i >= n4) return;
    float4 v = reinterpret_cast<const float4*>(src)[i];
    uint32_t h0, l0, h1, l1;
    split2(v.x, v.y, h0, l0);
    split2(v.z, v.w, h1, l1);
    reinterpret_cast<uint2*>(hi)[i] = make_uint2(h0, h1);
    reinterpret_cast<uint2*>(lo)[i] = make_uint2(l0, l1);
}

// ---------------------------------------------------------------------------
// Rotation-folded weight conversion for q/k rows (0..2047 of qkv_w)
// ---------------------------------------------------------------------------
__global__ void cvt_rot_kernel(const float* __restrict__ W,
                               __nv_bfloat16* __restrict__ hi)
{
    int i = blockIdx.x * blockDim.x + threadIdx.x;
    int row = i >> 8;             // 0..2047
    int c4  = (i & 255) * 4;
    int which = row >> 10;        // 0=q,1=k
    int o     = row & 1023;
    int partner; float sgn;
    if (o < 512) { partner = 2 * o + 1;       sgn = -1.f; }
    else         { partner = 2 * (o - 512);   sgn =  1.f; }
    float cv = g_cos[o], sv = g_sin[o] * sgn;

    const float4 a = *reinterpret_cast<const float4*>(W + ((size_t)(which * 1024 + o)       * Esz) + c4);
    const float4 b = *reinterpret_cast<const float4*>(W + ((size_t)(which * 1024 + partner) * Esz) + c4);
    float r0 = cv * a.x + sv * b.x;
    float r1 = cv * a.y + sv * b.y;
    float r2 = cv * a.z + sv * b.z;
    float r3 = cv * a.w + sv * b.w;
    uint32_t h0 = packbf(__bfloat162float(__float2bfloat16_rn(r0)),
                         __bfloat162float(__float2bfloat16_rn(r1)));
    uint32_t h1 = packbf(__bfloat162float(__float2bfloat16_rn(r2)),
                         __bfloat162float(__float2bfloat16_rn(r3)));
    *reinterpret_cast<uint2*>(hi + (size_t)row * Esz + c4) = make_uint2(h0, h1);
}

// rotated qk bias
__global__ void rotbias_kernel(const float* __restrict__ b, float* __restrict__ b2)
{
    int row = blockIdx.x * blockDim.x + threadIdx.x;
    if (row >= 2048) return;
    int which = row >> 10;
    int o     = row & 1023;
    int partner; float sgn;
    if (o < 512) { partner = 2 * o + 1;     sgn = -1.f; }
    else         { partner = 2 * (o - 512); sgn =  1.f; }
    b2[row] = g_cos[o] * b[which * 1024 + o] + sgn * g_sin[o] * b[which * 1024 + partner];
}

// ---------------------------------------------------------------------------
// sin/cos precompute
// ---------------------------------------------------------------------------
__global__ void sincos_kernel(const float* __restrict__ inv_freq)
{
    int i = blockIdx.x * blockDim.x + threadIdx.x;
    if (i < Esz) {
        float arg = 2048.0f * inv_freq[i];
        double a = (double)arg;
        g_sin[i] = (float)sin(a);
        g_cos[i] = (float)cos(a);
    }
}

// ---------------------------------------------------------------------------
// bf16 GEMM (3-term split), cp.async double buffer, LDSM. For V and out-proj.
// ---------------------------------------------------------------------------
#define GBM 128
#define GBN 128
#define GBK 32
#define GP  40
#define GTSZ (GBM * GP)
#define GEMM_SMEM3 (2 * 4 * GTSZ * 2)   // 81920
#define GEMM_SMEM1 (2 * 2 * GTSZ * 2)   // 40960

__global__ __launch_bounds__(256) void mma_gemm_split3(
    const __nv_bfloat16* __restrict__ Agh, const __nv_bfloat16* __restrict__ Agl,
    const __nv_bfloat16* __restrict__ Bgh, const __nv_bfloat16* __restrict__ Bgl,
    const float* __restrict__ bias, float* __restrict__ C,
    int ldc, int K)
{
    extern __shared__ __nv_bfloat16 S[];

    int tid  = threadIdx.x;
    int lane = tid & 31;
    int w    = tid >> 5;
    int wm   = (w >> 2) * 64;
    int wn   = (w & 3) * 32;
    int bm   = blockIdx.y * GBM;
    int bn   = blockIdx.x * GBN;
    int g    = lane >> 2;
    int cp   = (lane & 3) * 2;

    int lA_r = lane & 15;
    int lA_c = (lane >> 4) << 3;
    int lB_r = ((lane >> 4) << 3) + (lane & 7);
    int lB_c = ((lane >> 3) & 1) << 3;

    auto load_tile = [&](int t, int st) {
        int k0 = t * GBK;
        #pragma unroll
        for (int a = 0; a < 4; a++) {
            const __nv_bfloat16* gsrc = (a == 0) ? Agh : (a == 1) ? Agl : (a == 2) ? Bgh : Bgl;
            int rowbase = (a < 2) ? bm : bn;
            __nv_bfloat16* dst = S + (st * 4 + a) * GTSZ;
            #pragma unroll
            for (int u = 0; u < 2; u++) {
                int idx = tid + u * 256;
                int r   = idx >> 2;
                int c8  = (idx & 3) * 8;
                cp_async16(dst + r * GP + c8, gsrc + (size_t)(rowbase + r) * K + k0 + c8);
            }
        }
    };

    float acc[4][4][4];
    #pragma unroll
    for (int i = 0; i < 4; i++)
        #pragma unroll
        for (int j = 0; j < 4; j++)
            #pragma unroll
            for (int q = 0; q < 4; q++) acc[i][j][q] = 0.f;

    int nk = K / GBK;
    load_tile(0, 0);
    CP_COMMIT();

    for (int t = 0; t < nk; t++) {
        int st = t & 1;
        if (t + 1 < nk) { load_tile(t + 1, st ^ 1); CP_COMMIT(); CP_WAIT(1); }
        else            { CP_WAIT(0); }
        __syncthreads();

        const __nv_bfloat16* Ah = S + (st * 4 + 0) * GTSZ;
        const __nv_bfloat16* Al = S + (st * 4 + 1) * GTSZ;
        const __nv_bfloat16* Bh = S + (st * 4 + 2) * GTSZ;
        const __nv_bfloat16* Bl = S + (st * 4 + 3) * GTSZ;

        #pragma unroll
        for (int ks = 0; ks < 2; ks++) {
            int k16 = ks * 16;
            uint32_t bh[4][2], bl[4][2];
            #pragma unroll
            for (int np = 0; np < 2; np++) {
                int nbase = wn + np * 16;
                ldsm_x4(bh[2*np][0], bh[2*np][1], bh[2*np+1][0], bh[2*np+1][1],
                        &Bh[(nbase + lB_r) * GP + k16 + lB_c]);
                ldsm_x4(bl[2*np][0], bl[2*np][1], bl[2*np+1][0], bl[2*np+1][1],
                        &Bl[(nbase + lB_r) * GP + k16 + lB_c]);
            }
            #pragma unroll
            for (int mt = 0; mt < 4; mt++) {
                int r = wm + mt * 16;
                uint32_t ah0, ah1, ah2, ah3, al0, al1, al2, al3;
                ldsm_x4(ah0, ah1, ah2, ah3, &Ah[(r + lA_r) * GP + k16 + lA_c]);
                ldsm_x4(al0, al1, al2, al3, &Al[(r + lA_r) * GP + k16 + lA_c]);
                #pragma unroll
                for (int nt = 0; nt < 4; nt++) {
                    mma_bf16(acc[mt][nt], ah0, ah1, ah2, ah3, bh[nt][0], bh[nt][1]);
                    mma_bf16(acc[mt][nt], ah0, ah1, ah2, ah3, bl[nt][0], bl[nt][1]);
                    mma_bf16(acc[mt][nt], al0, al1, al2, al3, bh[nt][0], bh[nt][1]);
                }
            }
        }
        __syncthreads();
    }

    #pragma unroll
    for (int mt = 0; mt < 4; mt++) {
        int row = bm + wm + mt * 16 + g;
        #pragma unroll
        for (int nt = 0; nt < 4; nt++) {
            int col = bn + wn + nt * 8 + cp;
            float2 o0, o1;
            o0.x = acc[mt][nt][0] + bias[col];
            o0.y = acc[mt][nt][1] + bias[col + 1];
            o1.x = acc[mt][nt][2] + bias[col];
            o1.y = acc[mt][nt][3] + bias[col + 1];
            *reinterpret_cast<float2*>(C + (size_t)row * ldc + col) = o0;
            *reinterpret_cast<float2*>(C + (size_t)(row + 8) * ldc + col) = o1;
        }
    }
}

// ---------------------------------------------------------------------------
// QK GEMM (hi-only) with fused per-head L2-norm epilogue.
// ---------------------------------------------------------------------------
__global__ __launch_bounds__(256) void mma_gemm_qk_norm(
    const __nv_bfloat16* __restrict__ Agh, const __nv_bfloat16* __restrict__ Bgh,
    const float* __restrict__ bias2, const float* __restrict__ scale_ptr,
    __nv_bfloat16* __restrict__ Qh, __nv_bfloat16* __restrict__ Kh, int K)
{
    extern __shared__ __nv_bfloat16 S[];
    __shared__ float sp[128][5];

    int tid  = threadIdx.x;
    int lane = tid & 31;
    int w    = tid >> 5;
    int wm   = (w >> 2) * 64;
    int wc   = w & 3;
    int wn   = wc * 32;
    int bm   = blockIdx.y * GBM;
    int bn   = blockIdx.x * GBN;
    int g    = lane >> 2;
    int cp   = (lane & 3) * 2;

    int lA_r = lane & 15;
    int lA_c = (lane >> 4) << 3;
    int lB_r = ((lane >> 4) << 3) + (lane & 7);
    int lB_c = ((lane >> 3) & 1) << 3;

    auto load_tile = [&](int t, int st) {
        int k0 = t * GBK;
        #pragma unroll
        for (int a = 0; a < 2; a++) {
            const __nv_bfloat16* gsrc = (a == 0) ? Agh : Bgh;
            int rowbase = (a == 0) ? bm : bn;
            __nv_bfloat16* dst = S + (st * 2 + a) * GTSZ;
            #pragma unroll
            for (int u = 0; u < 2; u++) {
                int idx = tid + u * 256;
                int r   = idx >> 2;
                int c8  = (idx & 3) * 8;
                cp_async16(dst + r * GP + c8, gsrc + (size_t)(rowbase + r) * K + k0 + c8);
            }
        }
    };

    float acc[4][4][4];
    #pragma unroll
    for (int i = 0; i < 4; i++)
        #pragma unroll
        for (int j = 0; j < 4; j++)
            #pragma unroll
            for (int q = 0; q < 4; q++) acc[i][j][q] = 0.f;

    int nk = K / GBK;
    load_tile(0, 0);
    CP_COMMIT();

    for (int t = 0; t < nk; t++) {
        int st = t & 1;
        if (t + 1 < nk) { load_tile(t + 1, st ^ 1); CP_COMMIT(); CP_WAIT(1); }
        else            { CP_WAIT(0); }
        __syncthreads();

        const __nv_bfloat16* Ah = S + (st * 2 + 0) * GTSZ;
        const __nv_bfloat16* Bh = S + (st * 2 + 1) * GTSZ;

        #pragma unroll
        for (int ks = 0; ks < 2; ks++) {
            int k16 = ks * 16;
            uint32_t bh[4][2];
            #pragma unroll
            for (int np = 0; np < 2; np++) {
                int nbase = wn + np * 16;
                ldsm_x4(bh[2*np][0], bh[2*np][1], bh[2*np+1][0], bh[2*np+1][1],
                        &Bh[(nbase + lB_r) * GP + k16 + lB_c]);
            }
            #pragma unroll
            for (int mt = 0; mt < 4; mt++) {
                int r = wm + mt * 16;
                uint32_t ah0, ah1, ah2, ah3;
                ldsm_x4(ah0, ah1, ah2, ah3, &Ah[(r + lA_r) * GP + k16 + lA_c]);
                #pragma unroll
                for (int nt = 0; nt < 4; nt++)
                    mma_bf16(acc[mt][nt], ah0, ah1, ah2, ah3, bh[nt][0], bh[nt][1]);
            }
        }
        __syncthreads();
    }

    #pragma unroll
    for (int mt = 0; mt < 4; mt++) {
        #pragma unroll
        for (int nt = 0; nt < 4; nt++) {
            int col = bn + wn + nt * 8 + cp;
            float b0 = bias2[col], b1 = bias2[col + 1];
            acc[mt][nt][0] += b0; acc[mt][nt][1] += b1;
            acc[mt][nt][2] += b0; acc[mt][nt][3] += b1;
        }
    }
    #pragma unroll
    for (int mt = 0; mt < 4; mt++) {
        float p0 = 0.f, p1 = 0.f;
        #pragma unroll
        for (int nt = 0; nt < 4; nt++) {
            p0 += acc[mt][nt][0] * acc[mt][nt][0] + acc[mt][nt][1] * acc[mt][nt][1];
            p1 += acc[mt][nt][2] * acc[mt][nt][2] + acc[mt][nt][3] * acc[mt][nt][3];
        }
        p0 += __shfl_xor_sync(0xffffffffu, p0, 1, 4);
        p0 += __shfl_xor_sync(0xffffffffu, p0, 2, 4);
        p1 += __shfl_xor_sync(0xffffffffu, p1, 1, 4);
        p1 += __shfl_xor_sync(0xffffffffu, p1, 2, 4);
        if ((lane & 3) == 0) {
            sp[wm + mt * 16 + g][wc]     = p0;
            sp[wm + mt * 16 + g + 8][wc] = p1;
        }
    }
    __syncthreads();

    float qscale = *scale_ptr;
    int hd2 = (wc >> 1) << 1;
    #pragma unroll
    for (int mt = 0; mt < 4; mt++) {
        int r0 = wm + mt * 16 + g;
        int r1 = r0 + 8;
        float n0 = sp[r0][hd2] + sp[r0][hd2 + 1];
        float n1 = sp[r1][hd2] + sp[r1][hd2 + 1];
        float i0 = qscale / fmaxf(sqrtf(n0), 1e-12f);
        float i1 = qscale / fmaxf(sqrtf(n1), 1e-12f);
        #pragma unroll
        for (int nt = 0; nt < 4; nt++) {
            int colg = bn + wn + nt * 8 + cp;
            __nv_bfloat16* outp = (colg < 1024) ? Qh : Kh;
            int colq = colg & 1023;
            uint32_t v0 = packbf(acc[mt][nt][0] * i0, acc[mt][nt][1] * i0);
            uint32_t v1 = packbf(acc[mt][nt][2] * i1, acc[mt][nt][3] * i1);
            *reinterpret_cast<uint32_t*>(outp + (size_t)(bm + r0) * Esz + colq) = v0;
            *reinterpret_cast<uint32_t*>(outp + (size_t)(bm + r1) * Esz + colq) = v1;
        }
    }
}

// ---------------------------------------------------------------------------
// V transpose per head (reads compact vf [tok][1024]): vth, pvs, ts.
// ---------------------------------------------------------------------------
__global__ void vtrans_kernel(const float* __restrict__ vf,
                              __nv_bfloat16* __restrict__ vth,
                              float* __restrict__ ts,
                              float* __restrict__ pvs)
{
    __shared__ float sv[64][65];
    int kt = blockIdx.x;
    int bh = blockIdx.y;
    int b  = bh >> 4;
    int h  = bh & 15;
    int s0 = kt * 64;
    int tid = threadIdx.x;

    const float* Vb = vf + ((size_t)(b * Ssz + s0)) * Esz + h * Dsz;
    #pragma unroll
    for (int u = 0; u < 4; u++) {
        int idx = tid + u * 256;
        int r   = idx >> 4;
        int c4  = (idx & 15) * 4;
        float4 v = *reinterpret_cast<const float4*>(Vb + (size_t)r * Esz + c4);
        sv[c4 + 0][r] = v.x;
        sv[c4 + 1][r] = v.y;
        sv[c4 + 2][r] = v.z;
        sv[c4 + 3][r] = v.w;
    }
    __syncthreads();

    size_t base = ((size_t)bh * Dsz) * Ssz + s0;
    #pragma unroll
    for (int u = 0; u < 4; u++) {
        int idx = tid + u * 256;
        int d   = idx >> 4;
        int s4  = (idx & 15) * 4;
        uint32_t h0 = packbf(sv[d][s4],     sv[d][s4 + 1]);
        uint32_t h1 = packbf(sv[d][s4 + 2], sv[d][s4 + 3]);
        *reinterpret_cast<uint2*>(vth + base + (size_t)d * Ssz + s4) = make_uint2(h0, h1);
    }
    __syncthreads();

    if (tid < 64) {
        float acc = 0.f;
        #pragma unroll
        for (int r = 0; r < 64; r++) { acc += sv[tid][r]; sv[tid][r] = acc; }
        ts[((size_t)bh * NKT + kt) * Dsz + tid] = acc;
    }
    __syncthreads();

    size_t pbase = ((size_t)bh * Ssz + s0) * Dsz;
    #pragma unroll
    for (int u = 0; u < 4; u++) {
        int idx = tid + u * 256;
        int r   = idx >> 4;
        int c4  = (idx & 15) * 4;
        float4 f;
        f.x = sv[c4 + 0][r]; f.y = sv[c4 + 1][r];
        f.z = sv[c4 + 2][r]; f.w = sv[c4 + 3][r];
        *reinterpret_cast<float4*>(pvs + pbase + (size_t)r * Dsz + c4) = f;
    }
}

// ---------------------------------------------------------------------------
// Exclusive prefix over tile sums
// ---------------------------------------------------------------------------
__global__ void ts_prefix_kernel(const float* __restrict__ ts,
                                 float* __restrict__ epts)
{
    int bh = blockIdx.x;
    int d  = threadIdx.x;
    float acc = 0.f;
    for (int kt = 0; kt < NKT; kt++) {
        epts[((size_t)bh * NKT + kt) * Dsz + d] = acc;
        acc += ts[((size_t)bh * NKT + kt) * Dsz + d];
    }
}

// ---------------------------------------------------------------------------
// Flash attention via uniform-softmax decomposition (round-11 notes).
// qt0 selects the q-tile range (split launches for out-GEMM overlap).
// ---------------------------------------------------------------------------
#define AP 72
#define ATSZ (64 * AP)
#define ATTN_SMEM (2 * 2 * ATSZ * 2)

__global__ __launch_bounds__(256) void attn_mma_kernel(
    const __nv_bfloat16* __restrict__ Qh, const __nv_bfloat16* __restrict__ Kh,
    const __nv_bfloat16* __restrict__ Vth,
    const float* __restrict__ epts, const float* __restrict__ pvs,
    __nv_bfloat16* __restrict__ Oh, __nv_bfloat16* __restrict__ Ol, int qt0)
{
    extern __shared__ __nv_bfloat16 SA[];

    int bh = blockIdx.y;
    int b  = bh >> 4;
    int h  = bh & 15;
    int qt = qt0 + (gridDim.x - 1) - blockIdx.x;   // largest first within range

    int tid  = threadIdx.x;
    int lane = tid & 31;
    int w    = tid >> 5;
    int g    = lane >> 2;
    int cp   = (lane & 3) * 2;

    int lB_r = ((lane >> 4) << 3) + (lane & 7);
    int lB_c = ((lane >> 3) & 1) << 3;

    int qrow0 = qt * 128 + w * 16;
    int row0  = qrow0 + g;
    int row1  = row0 + 8;
    int wmax  = qrow0 + 15;

    const __nv_bfloat16* Kb  = Kh  + ((size_t)b * Ssz) * Esz + h * Dsz;
    const __nv_bfloat16* Vbh = Vth + ((size_t)bh * Dsz) * Ssz;

    auto load_tile = [&](int kt, int st) {
        int kbase = kt * 64;
        __nv_bfloat16* Ks = SA + st * 2 * ATSZ;
        __nv_bfloat16* Vh = Ks + ATSZ;
        #pragma unroll
        for (int u = 0; u < 4; u++) {
            int idx  = tid + u * 256;
            int a    = idx >> 9;
            int idx2 = idx & 511;
            int rr   = idx2 >> 3;
            int c8   = (idx2 & 7) * 8;
            if (a == 0)
                cp_async16(Ks + rr * AP + c8, Kb + (size_t)(kbase + rr) * Esz + c8);
            else
                cp_async16(Vh + rr * AP + c8, Vbh + (size_t)rr * Ssz + kbase + c8);
        }
    };

    uint32_t aQ[4][4];
    const __nv_bfloat16* Qb = Qh + ((size_t)(b * Ssz + qrow0)) * Esz + h * Dsz;
    #pragma unroll
    for (int ks = 0; ks < 4; ks++) {
        int c = ks * 16 + cp;
        aQ[ks][0] = *reinterpret_cast<const uint32_t*>(Qb + (size_t)g * Esz + c);
        aQ[ks][1] = *reinterpret_cast<const uint32_t*>(Qb + (size_t)(g + 8) * Esz + c);
        aQ[ks][2] = *reinterpret_cast<const uint32_t*>(Qb + (size_t)g * Esz + c + 8);
        aQ[ks][3] = *reinterpret_cast<const uint32_t*>(Qb + (size_t)(g + 8) * Esz + c + 8);
    }

    float o[8][4];
    #pragma unroll
    for (int i = 0; i < 8; i++)
        #pragma unroll
        for (int j = 0; j < 4; j++) o[i][j] = 0.f;
    float l0 = 0.f, l1 = 0.f;

    int ktmax = qt * 2 + 1;
    load_tile(0, 0);
    CP_COMMIT();

    for (int kt = 0; kt <= ktmax; kt++) {
        int st = kt & 1;
        if (kt + 1 <= ktmax) { load_tile(kt + 1, st ^ 1); CP_COMMIT(); CP_WAIT(1); }
        else                 { CP_WAIT(0); }
        __syncthreads();

        int kbase = kt * 64;
        if (kbase <= wmax) {
            const __nv_bfloat16* Ks = SA + st * 2 * ATSZ;
            const __nv_bfloat16* Vh = Ks + ATSZ;

            float sc[8][4];
            #pragma unroll
            for (int nt = 0; nt < 8; nt++)
                #pragma unroll
                for (int j = 0; j < 4; j++) sc[nt][j] = 0.f;
            #pragma unroll
            for (int ks = 0; ks < 4; ks++) {
                int k16 = ks * 16;
                uint32_t bk[8][2];
                #pragma unroll
                for (int np = 0; np < 4; np++)
                    ldsm_x4(bk[2*np][0], bk[2*np][1], bk[2*np+1][0], bk[2*np+1][1],
                            &Ks[(np * 16 + lB_r) * AP + k16 + lB_c]);
                #pragma unroll
                for (int nt = 0; nt < 8; nt++)
                    mma_bf16(sc[nt], aQ[ks][0], aQ[ks][1], aQ[ks][2], aQ[ks][3],
                             bk[nt][0], bk[nt][1]);
            }

            float ps0 = 0.f, ps1 = 0.f;
            #pragma unroll
            for (int nt = 0; nt < 8; nt++) {
                int c0 = kbase + nt * 8 + cp;
                float x0 = sc[nt][0], x1 = sc[nt][1], x2 = sc[nt][2], x3 = sc[nt][3];
                float d0 = x0 * (1.f + x0 * (0.5f + x0 * (1.f / 6.f)));
                float d1 = x1 * (1.f + x1 * (0.5f + x1 * (1.f / 6.f)));
                float d2 = x2 * (1.f + x2 * (0.5f + x2 * (1.f / 6.f)));
                float d3 = x3 * (1.f + x3 * (0.5f + x3 * (1.f / 6.f)));
                if (c0     > row0) d0 = 0.f;
                if (c0 + 1 > row0) d1 = 0.f;
                if (c0     > row1) d2 = 0.f;
                if (c0 + 1 > row1) d3 = 0.f;
                sc[nt][0] = d0; sc[nt][1] = d1; sc[nt][2] = d2; sc[nt][3] = d3;
                ps0 += d0 + d1;
                ps1 += d2 + d3;
            }
            l0 += ps0; l1 += ps1;

            uint32_t aP[4][4];
            #pragma unroll
            for (int kk = 0; kk < 4; kk++) {
                aP[kk][0] = packbf(sc[2*kk][0],   sc[2*kk][1]);
                aP[kk][1] = packbf(sc[2*kk][2],   sc[2*kk][3]);
                aP[kk][2] = packbf(sc[2*kk+1][0], sc[2*kk+1][1]);
                aP[kk][3] = packbf(sc[2*kk+1][2], sc[2*kk+1][3]);
            }

            #pragma unroll
            for (int kk = 0; kk < 4; kk++) {
                int k16 = kk * 16;
                uint32_t bv[8][2];
                #pragma unroll
                for (int np = 0; np < 4; np++)
                    ldsm_x4(bv[2*np][0], bv[2*np][1], bv[2*np+1][0], bv[2*np+1][1],
                            &Vh[(np * 16 + lB_r) * AP + k16 + lB_c]);
                #pragma unroll
                for (int dt = 0; dt < 8; dt++)
                    mma_bf16(o[dt], aP[kk][0], aP[kk][1], aP[kk][2], aP[kk][3],
                             bv[dt][0], bv[dt][1]);
            }
        }
        __syncthreads();
    }

    l0 += __shfl_xor_sync(0xffffffffu, l0, 1, 4);
    l0 += __shfl_xor_sync(0xffffffffu, l0, 2, 4);
    l1 += __shfl_xor_sync(0xffffffffu, l1, 1, 4);
    l1 += __shfl_xor_sync(0xffffffffu, l1, 2, 4);
    float i0 = 1.0f / ((float)(row0 + 1) + l0);
    float i1 = 1.0f / ((float)(row1 + 1) + l1);

    const float* ep0 = epts + ((size_t)bh * NKT + (row0 >> 6)) * Dsz;
    const float* ep1 = epts + ((size_t)bh * NKT + (row1 >> 6)) * Dsz;
    const float* pv0 = pvs + ((size_t)bh * Ssz + row0) * Dsz;
    const float* pv1 = pvs + ((size_t)bh * Ssz + row1) * Dsz;

    __nv_bfloat16* Ohb = Oh + ((size_t)(b * Ssz + qrow0)) * Esz + h * Dsz;
    __nv_bfloat16* Olb = Ol + ((size_t)(b * Ssz + qrow0)) * Esz + h * Dsz;
    #pragma unroll
    for (int dt = 0; dt < 8; dt++) {
        int c = dt * 8 + cp;
        float a0 = ep0[c]     + pv0[c];
        float a1 = ep0[c + 1] + pv0[c + 1];
        float b0 = ep1[c]     + pv1[c];
        float b1 = ep1[c + 1] + pv1[c + 1];
        uint32_t h0, lo0, h1, lo1;
        split2((o[dt][0] + a0) * i0, (o[dt][1] + a1) * i0, h0, lo0);
        split2((o[dt][2] + b0) * i1, (o[dt][3] + b1) * i1, h1, lo1);
        *reinterpret_cast<uint32_t*>(Ohb + (size_t)g * Esz + c)       = h0;
        *reinterpret_cast<uint32_t*>(Olb + (size_t)g * Esz + c)       = lo0;
        *reinterpret_cast<uint32_t*>(Ohb + (size_t)(g + 8) * Esz + c) = h1;
        *reinterpret_cast<uint32_t*>(Olb + (size_t)(g + 8) * Esz + c) = lo1;
    }
}

// ---------------------------------------------------------------------------
extern "C" void kernel_launch(void* const* d_in, const int* in_sizes, int n_in,
                              void* d_out, int out_size)
{
    const float* x       = (const float*)d_in[0];
    const float* ln_w    = (const float*)d_in[1];
    const float* ln_b    = (const float*)d_in[2];
    const float* qkv_w   = (const float*)d_in[3];
    const float* qkv_b   = (const float*)d_in[4];
    const float* qk_scal = (const float*)d_in[5];
    const float* out_w   = (const float*)d_in[6];
    const float* out_b   = (const float*)d_in[7];
    const float* invfreq = (const float*)d_in[8];
    float* out = (float*)d_out;

    float *vf, *ts, *epts, *pvs, *qb2;
    cudaGetSymbolAddress((void**)&vf,   g_vf);
    cudaGetSymbolAddress((void**)&ts,   g_ts);
    cudaGetSymbolAddress((void**)&epts, g_epts);
    cudaGetSymbolAddress((void**)&pvs,  g_pvs);
    cudaGetSymbolAddress((void**)&qb2,  g_qb2);
    __nv_bfloat16 *xnh, *xnl, *wqh, *wql, *woh, *wol, *qh, *kh, *vth, *ath, *atl;
    cudaGetSymbolAddress((void**)&xnh, g_xnh);
    cudaGetSymbolAddress((void**)&xnl, g_xnl);
    cudaGetSymbolAddress((void**)&wqh, g_wqh);
    cudaGetSymbolAddress((void**)&wql, g_wql);
    cudaGetSymbolAddress((void**)&woh, g_woh);
    cudaGetSymbolAddress((void**)&wol, g_wol);
    cudaGetSymbolAddress((void**)&qh,  g_qh);
    cudaGetSymbolAddress((void**)&kh,  g_kh);
    cudaGetSymbolAddress((void**)&vth, g_vth);
    cudaGetSymbolAddress((void**)&ath, g_ath);
    cudaGetSymbolAddress((void**)&atl, g_atl);

    cudaFuncSetAttribute(mma_gemm_split3,
                         cudaFuncAttributeMaxDynamicSharedMemorySize, GEMM_SMEM3);
    cudaFuncSetAttribute(mma_gemm_qk_norm,
                         cudaFuncAttributeMaxDynamicSharedMemorySize, GEMM_SMEM1);
    cudaFuncSetAttribute(attn_mma_kernel,
                         cudaFuncAttributeMaxDynamicSharedMemorySize, ATTN_SMEM);

    static cudaStream_t s1 = nullptr, s2 = nullptr;
    static cudaEvent_t evStart = nullptr, evLN = nullptr, evRotW = nullptr,
                       evSide1 = nullptr, evSide2 = nullptr,
                       evAttnTop = nullptr, evOutA = nullptr;
    if (s1 == nullptr) {
        cudaStreamCreateWithFlags(&s1, cudaStreamNonBlocking);
        cudaStreamCreateWithFlags(&s2, cudaStreamNonBlocking);
        cudaEventCreateWithFlags(&evStart,   cudaEventDisableTiming);
        cudaEventCreateWithFlags(&evLN,      cudaEventDisableTiming);
        cudaEventCreateWithFlags(&evRotW,    cudaEventDisableTiming);
        cudaEventCreateWithFlags(&evSide1,   cudaEventDisableTiming);
        cudaEventCreateWithFlags(&evSide2,   cudaEventDisableTiming);
        cudaEventCreateWithFlags(&evAttnTop, cudaEventDisableTiming);
        cudaEventCreateWithFlags(&evOutA,    cudaEventDisableTiming);
    }
    cudaStream_t s0 = 0;

    // fork
    cudaEventRecord(evStart, s0);
    cudaStreamWaitEvent(s1, evStart, 0);
    cudaStreamWaitEvent(s2, evStart, 0);

    // s2: sincos -> rotation-folded QK weights + bias -> out_w split
    sincos_kernel<<<4, 256, 0, s2>>>(invfreq);
    cvt_rot_kernel<<<2048 * 256 / 256, 256, 0, s2>>>(qkv_w, wqh);
    rotbias_kernel<<<8, 256, 0, s2>>>(qkv_b, qb2);
    cudaEventRecord(evRotW, s2);
    cvt_split_kernel<<<(Esz * Esz / 4 + 255) / 256, 256, 0, s2>>>(out_w, woh, wol, Esz * Esz / 4);
    cudaEventRecord(evSide2, s2);

    // s1: V-weight split, then (after ln) V-GEMM -> vtrans -> ts_prefix
    cvt_split_kernel<<<(1024 * Esz / 4 + 255) / 256, 256, 0, s1>>>(
        qkv_w + (size_t)2048 * Esz, wqh + (size_t)2048 * Esz, wql + (size_t)2048 * Esz,
        1024 * Esz / 4);

    // s0: LN
    ln_kernel<<<TOK, 256, 0, s0>>>(x, ln_w, ln_b, xnh, xnl);
    cudaEventRecord(evLN, s0);

    // s1 continues after LN
    cudaStreamWaitEvent(s1, evLN, 0);
    mma_gemm_split3<<<dim3(1024 / GBN, TOK / GBM), 256, GEMM_SMEM3, s1>>>(
        xnh, xnl, wqh + (size_t)2048 * Esz, wql + (size_t)2048 * Esz,
        qkv_b + 2048, vf, Esz, Esz);
    vtrans_kernel<<<dim3(NKT, Bsz * Hsz), 256, 0, s1>>>(vf, vth, ts, pvs);
    ts_prefix_kernel<<<Bsz * Hsz, Dsz, 0, s1>>>(ts, epts);
    cudaEventRecord(evSide1, s1);

    // s0: QK GEMM with fused rotation + per-head L2 norm
    cudaStreamWaitEvent(s0, evRotW, 0);
    mma_gemm_qk_norm<<<dim3(2048 / GBN, TOK / GBM), 256, GEMM_SMEM1, s0>>>(
        xnh, wqh, qb2, qk_scal, qh, kh, Esz);

    // s0: attention top half (qt 8..15, long CTAs)
    cudaStreamWaitEvent(s0, evSide1, 0);
    attn_mma_kernel<<<dim3(8, Bsz * Hsz), 256, ATTN_SMEM, s0>>>(
        qh, kh, vth, epts, pvs, ath, atl, 8);
    cudaEventRecord(evAttnTop, s0);

    // s1: out-proj for top-half tokens, overlapping bottom-half attention
    cudaStreamWaitEvent(s1, evAttnTop, 0);
    cudaStreamWaitEvent(s1, evSide2, 0);
    mma_gemm_split3<<<dim3(Esz / GBN, 8), 256, GEMM_SMEM3, s1>>>(
        ath + (size_t)1024 * Esz, atl + (size_t)1024 * Esz, woh, wol,
        out_b, out + (size_t)1024 * Esz, Esz, Esz);
    mma_gemm_split3<<<dim3(Esz / GBN, 8), 256, GEMM_SMEM3, s1>>>(
        ath + (size_t)3072 * Esz, atl + (size_t)3072 * Esz, woh, wol,
        out_b, out + (size_t)3072 * Esz, Esz, Esz);
    cudaEventRecord(evOutA, s1);

    // s0: attention bottom half (qt 0..7), then its out-proj
    attn_mma_kernel<<<dim3(8, Bsz * Hsz), 256, ATTN_SMEM, s0>>>(
        qh, kh, vth, epts, pvs, ath, atl, 0);
    cudaStreamWaitEvent(s0, evSide2, 0);
    mma_gemm_split3<<<dim3(Esz / GBN, 8), 256, GEMM_SMEM3, s0>>>(
        ath, atl, woh, wol, out_b, out, Esz, Esz);
    mma_gemm_split3<<<dim3(Esz / GBN, 8), 256, GEMM_SMEM3, s0>>>(
        ath + (size_t)2048 * Esz, atl + (size_t)2048 * Esz, woh, wol,
        out_b, out + (size_t)2048 * Esz, Esz, Esz);

    // final join
    cudaStreamWaitEvent(s0, evOutA, 0);
}

// round 17
// speedup vs baseline: 1.1240x; 1.1240x over previous
#include <cuda_runtime.h>
#include <cuda_bf16.h>
#include <cstdint>
#include <math.h>

// Problem constants
#define Bsz 2
#define Ssz 2048
#define Esz 1024
#define Hsz 16
#define Dsz 64
#define TOK (Bsz*Ssz)        // 4096 tokens
#define E3  (3*Esz)          // 3072
#define NKT (Ssz/64)         // 32 key tiles per sequence

// Scratch (static device globals — no allocation)
__device__ float        g_vf  [ (size_t)TOK * Esz ];    // fp32 V output (compact)
__device__ __nv_bfloat16 g_xnh [ (size_t)TOK * Esz ];
__device__ __nv_bfloat16 g_xnl [ (size_t)TOK * Esz ];
__device__ __nv_bfloat16 g_wqh [ (size_t)E3  * Esz ];   // rows 0..2047 = ROTATED qk W, 2048.. = V hi
__device__ __nv_bfloat16 g_wql [ (size_t)E3  * Esz ];   // only V rows used
__device__ __nv_bfloat16 g_woh [ (size_t)Esz * Esz ];
__device__ __nv_bfloat16 g_wol [ (size_t)Esz * Esz ];
__device__ __nv_bfloat16 g_qh  [ (size_t)TOK * Esz ];
__device__ __nv_bfloat16 g_kh  [ (size_t)TOK * Esz ];
__device__ __nv_bfloat16 g_vth [ (size_t)TOK * Esz ];   // [bh][d][S]
__device__ __nv_bfloat16 g_ath [ (size_t)TOK * Esz ];
__device__ __nv_bfloat16 g_atl [ (size_t)TOK * Esz ];
__device__ float g_ts  [ (size_t)Bsz * Hsz * NKT * Dsz ];
__device__ float g_epts[ (size_t)Bsz * Hsz * NKT * Dsz ];
__device__ float g_pvs [ (size_t)Bsz * Hsz * Ssz * Dsz ];
__device__ float g_qb2 [ 2 * Esz ];                     // rotated qk bias
__device__ float g_sin [ Esz ];
__device__ float g_cos [ Esz ];

// ---------------------------------------------------------------------------
// helpers
// ---------------------------------------------------------------------------
__device__ __forceinline__ void mma_bf16(float* d,
                                         uint32_t a0, uint32_t a1, uint32_t a2, uint32_t a3,
                                         uint32_t b0, uint32_t b1)
{
    asm volatile("mma.sync.aligned.m16n8k16.row.col.f32.bf16.bf16.f32 "
        "{%0,%1,%2,%3}, {%4,%5,%6,%7}, {%8,%9}, {%0,%1,%2,%3};"
        : "+f"(d[0]), "+f"(d[1]), "+f"(d[2]), "+f"(d[3])
        : "r"(a0), "r"(a1), "r"(a2), "r"(a3), "r"(b0), "r"(b1));
}

__device__ __forceinline__ void ldsm_x4(uint32_t& r0, uint32_t& r1,
                                        uint32_t& r2, uint32_t& r3,
                                        const void* smem_ptr)
{
    uint32_t addr = (uint32_t)__cvta_generic_to_shared(smem_ptr);
    asm volatile("ldmatrix.sync.aligned.m8n8.x4.shared.b16 {%0,%1,%2,%3}, [%4];"
                 : "=r"(r0), "=r"(r1), "=r"(r2), "=r"(r3) : "r"(addr));
}

__device__ __forceinline__ uint32_t packbf(float lo, float hi)
{
    __nv_bfloat162 t = __floats2bfloat162_rn(lo, hi);
    return *reinterpret_cast<uint32_t*>(&t);
}

__device__ __forceinline__ void split2(float a, float b, uint32_t& hi, uint32_t& lo)
{
    float ha = __bfloat162float(__float2bfloat16_rn(a));
    float hb = __bfloat162float(__float2bfloat16_rn(b));
    hi = packbf(ha, hb);
    lo = packbf(a - ha, b - hb);
}

__device__ __forceinline__ void cp_async16(void* smem_dst, const void* gmem_src)
{
    uint32_t s = (uint32_t)__cvta_generic_to_shared(smem_dst);
    asm volatile("cp.async.cg.shared.global [%0], [%1], 16;" :: "r"(s), "l"(gmem_src));
}
#define CP_COMMIT()  asm volatile("cp.async.commit_group;")
#define CP_WAIT(n)   asm volatile("cp.async.wait_group %0;" :: "n"(n))

// ---------------------------------------------------------------------------
// LayerNorm -> hi/lo bf16 directly. One block per token, 256 threads.
// ---------------------------------------------------------------------------
__global__ void ln_kernel(const float* __restrict__ x,
                          const float* __restrict__ w,
                          const float* __restrict__ b,
                          __nv_bfloat16* __restrict__ oh,
                          __nv_bfloat16* __restrict__ ol)
{
    int t   = blockIdx.x;
    int tid = threadIdx.x;
    const float4* xr = reinterpret_cast<const float4*>(x + (size_t)t * Esz);
    float4 v = xr[tid];

    float s  = v.x + v.y + v.z + v.w;
    float ss = v.x*v.x + v.y*v.y + v.z*v.z + v.w*v.w;
    #pragma unroll
    for (int off = 16; off; off >>= 1) {
        s  += __shfl_xor_sync(0xffffffffu, s,  off);
        ss += __shfl_xor_sync(0xffffffffu, ss, off);
    }
    __shared__ float red[16];
    int wid = tid >> 5;
    if ((tid & 31) == 0) { red[wid] = s; red[8 + wid] = ss; }
    __syncthreads();
    float tot = 0.f, tot2 = 0.f;
    #pragma unroll
    for (int i = 0; i < 8; i++) { tot += red[i]; tot2 += red[8 + i]; }

    float mu   = tot * (1.0f / Esz);
    float var  = tot2 * (1.0f / Esz) - mu * mu;
    float rstd = rsqrtf(var + 1e-5f);

    const float4 wv = reinterpret_cast<const float4*>(w)[tid];
    const float4 bv = reinterpret_cast<const float4*>(b)[tid];
    float o0 = (v.x - mu) * rstd * wv.x + bv.x;
    float o1 = (v.y - mu) * rstd * wv.y + bv.y;
    float o2 = (v.z - mu) * rstd * wv.z + bv.z;
    float o3 = (v.w - mu) * rstd * wv.w + bv.w;

    uint32_t h0, l0, h1, l1;
    split2(o0, o1, h0, l0);
    split2(o2, o3, h1, l1);
    reinterpret_cast<uint2*>(oh + (size_t)t * Esz)[tid] = make_uint2(h0, h1);
    reinterpret_cast<uint2*>(ol + (size_t)t * Esz)[tid] = make_uint2(l0, l1);
}

// ---------------------------------------------------------------------------
// Elementwise fp32 -> hi/lo bf16 split
// ---------------------------------------------------------------------------
__global__ void cvt_split_kernel(const float* __restrict__ src,
                                 __nv_bfloat16* __restrict__ hi,
                                 __nv_bfloat16* __restrict__ lo, int n4)
{
    int i = blockIdx.x * blockDim.x + threadIdx.x;
    if (i >= n4) return;
    float4 v = reinterpret_cast<const float4*>(src)[i];
    uint32_t h0, l0, h1, l1;
    split2(v.x, v.y, h0, l0);
    split2(v.z, v.w, h1, l1);
    reinterpret_cast<uint2*>(hi)[i] = make_uint2(h0, h1);
    reinterpret_cast<uint2*>(lo)[i] = make_uint2(l0, l1);
}

// ---------------------------------------------------------------------------
// Rotation-folded weight conversion for q/k rows (0..2047 of qkv_w)
// ---------------------------------------------------------------------------
__global__ void cvt_rot_kernel(const float* __restrict__ W,
                               __nv_bfloat16* __restrict__ hi)
{
    int i = blockIdx.x * blockDim.x + threadIdx.x;
    int row = i >> 8;             // 0..2047
    int c4  = (i & 255) * 4;
    int which = row >> 10;        // 0=q,1=k
    int o     = row & 1023;
    int partner; float sgn;
    if (o < 512) { partner = 2 * o + 1;       sgn = -1.f; }
    else         { partner = 2 * (o - 512);   sgn =  1.f; }
    float cv = g_cos[o], sv = g_sin[o] * sgn;

    const float4 a = *reinterpret_cast<const float4*>(W + ((size_t)(which * 1024 + o)       * Esz) + c4);
    const float4 b = *reinterpret_cast<const float4*>(W + ((size_t)(which * 1024 + partner) * Esz) + c4);
    float r0 = cv * a.x + sv * b.x;
    float r1 = cv * a.y + sv * b.y;
    float r2 = cv * a.z + sv * b.z;
    float r3 = cv * a.w + sv * b.w;
    uint32_t h0 = packbf(__bfloat162float(__float2bfloat16_rn(r0)),
                         __bfloat162float(__float2bfloat16_rn(r1)));
    uint32_t h1 = packbf(__bfloat162float(__float2bfloat16_rn(r2)),
                         __bfloat162float(__float2bfloat16_rn(r3)));
    *reinterpret_cast<uint2*>(hi + (size_t)row * Esz + c4) = make_uint2(h0, h1);
}

// rotated qk bias
__global__ void rotbias_kernel(const float* __restrict__ b, float* __restrict__ b2)
{
    int row = blockIdx.x * blockDim.x + threadIdx.x;
    if (row >= 2048) return;
    int which = row >> 10;
    int o     = row & 1023;
    int partner; float sgn;
    if (o < 512) { partner = 2 * o + 1;     sgn = -1.f; }
    else         { partner = 2 * (o - 512); sgn =  1.f; }
    b2[row] = g_cos[o] * b[which * 1024 + o] + sgn * g_sin[o] * b[which * 1024 + partner];
}

// ---------------------------------------------------------------------------
// sin/cos precompute
// ---------------------------------------------------------------------------
__global__ void sincos_kernel(const float* __restrict__ inv_freq)
{
    int i = blockIdx.x * blockDim.x + threadIdx.x;
    if (i < Esz) {
        float arg = 2048.0f * inv_freq[i];
        double a = (double)arg;
        g_sin[i] = (float)sin(a);
        g_cos[i] = (float)cos(a);
    }
}

// ---------------------------------------------------------------------------
// bf16 GEMM (3-term split), cp.async double buffer, LDSM. For V and out-proj.
// ---------------------------------------------------------------------------
#define GBM 128
#define GBN 128
#define GBK 32
#define GP  40
#define GTSZ (GBM * GP)
#define GEMM_SMEM3 (2 * 4 * GTSZ * 2)   // 81920
#define GEMM_SMEM1 (2 * 2 * GTSZ * 2)   // 40960

__global__ __launch_bounds__(256) void mma_gemm_split3(
    const __nv_bfloat16* __restrict__ Agh, const __nv_bfloat16* __restrict__ Agl,
    const __nv_bfloat16* __restrict__ Bgh, const __nv_bfloat16* __restrict__ Bgl,
    const float* __restrict__ bias, float* __restrict__ C,
    int ldc, int K)
{
    extern __shared__ __nv_bfloat16 S[];

    int tid  = threadIdx.x;
    int lane = tid & 31;
    int w    = tid >> 5;
    int wm   = (w >> 2) * 64;
    int wn   = (w & 3) * 32;
    int bm   = blockIdx.y * GBM;
    int bn   = blockIdx.x * GBN;
    int g    = lane >> 2;
    int cp   = (lane & 3) * 2;

    int lA_r = lane & 15;
    int lA_c = (lane >> 4) << 3;
    int lB_r = ((lane >> 4) << 3) + (lane & 7);
    int lB_c = ((lane >> 3) & 1) << 3;

    auto load_tile = [&](int t, int st) {
        int k0 = t * GBK;
        #pragma unroll
        for (int a = 0; a < 4; a++) {
            const __nv_bfloat16* gsrc = (a == 0) ? Agh : (a == 1) ? Agl : (a == 2) ? Bgh : Bgl;
            int rowbase = (a < 2) ? bm : bn;
            __nv_bfloat16* dst = S + (st * 4 + a) * GTSZ;
            #pragma unroll
            for (int u = 0; u < 2; u++) {
                int idx = tid + u * 256;
                int r   = idx >> 2;
                int c8  = (idx & 3) * 8;
                cp_async16(dst + r * GP + c8, gsrc + (size_t)(rowbase + r) * K + k0 + c8);
            }
        }
    };

    float acc[4][4][4];
    #pragma unroll
    for (int i = 0; i < 4; i++)
        #pragma unroll
        for (int j = 0; j < 4; j++)
            #pragma unroll
            for (int q = 0; q < 4; q++) acc[i][j][q] = 0.f;

    int nk = K / GBK;
    load_tile(0, 0);
    CP_COMMIT();

    for (int t = 0; t < nk; t++) {
        int st = t & 1;
        if (t + 1 < nk) { load_tile(t + 1, st ^ 1); CP_COMMIT(); CP_WAIT(1); }
        else            { CP_WAIT(0); }
        __syncthreads();

        const __nv_bfloat16* Ah = S + (st * 4 + 0) * GTSZ;
        const __nv_bfloat16* Al = S + (st * 4 + 1) * GTSZ;
        const __nv_bfloat16* Bh = S + (st * 4 + 2) * GTSZ;
        const __nv_bfloat16* Bl = S + (st * 4 + 3) * GTSZ;

        #pragma unroll
        for (int ks = 0; ks < 2; ks++) {
            int k16 = ks * 16;
            uint32_t bh[4][2], bl[4][2];
            #pragma unroll
            for (int np = 0; np < 2; np++) {
                int nbase = wn + np * 16;
                ldsm_x4(bh[2*np][0], bh[2*np][1], bh[2*np+1][0], bh[2*np+1][1],
                        &Bh[(nbase + lB_r) * GP + k16 + lB_c]);
                ldsm_x4(bl[2*np][0], bl[2*np][1], bl[2*np+1][0], bl[2*np+1][1],
                        &Bl[(nbase + lB_r) * GP + k16 + lB_c]);
            }
            #pragma unroll
            for (int mt = 0; mt < 4; mt++) {
                int r = wm + mt * 16;
                uint32_t ah0, ah1, ah2, ah3, al0, al1, al2, al3;
                ldsm_x4(ah0, ah1, ah2, ah3, &Ah[(r + lA_r) * GP + k16 + lA_c]);
                ldsm_x4(al0, al1, al2, al3, &Al[(r + lA_r) * GP + k16 + lA_c]);
                #pragma unroll
                for (int nt = 0; nt < 4; nt++) {
                    mma_bf16(acc[mt][nt], ah0, ah1, ah2, ah3, bh[nt][0], bh[nt][1]);
                    mma_bf16(acc[mt][nt], ah0, ah1, ah2, ah3, bl[nt][0], bl[nt][1]);
                    mma_bf16(acc[mt][nt], al0, al1, al2, al3, bh[nt][0], bh[nt][1]);
                }
            }
        }
        __syncthreads();
    }

    #pragma unroll
    for (int mt = 0; mt < 4; mt++) {
        int row = bm + wm + mt * 16 + g;
        #pragma unroll
        for (int nt = 0; nt < 4; nt++) {
            int col = bn + wn + nt * 8 + cp;
            float2 o0, o1;
            o0.x = acc[mt][nt][0] + bias[col];
            o0.y = acc[mt][nt][1] + bias[col + 1];
            o1.x = acc[mt][nt][2] + bias[col];
            o1.y = acc[mt][nt][3] + bias[col + 1];
            *reinterpret_cast<float2*>(C + (size_t)row * ldc + col) = o0;
            *reinterpret_cast<float2*>(C + (size_t)(row + 8) * ldc + col) = o1;
        }
    }
}

// ---------------------------------------------------------------------------
// QK GEMM (hi-only) with fused per-head L2-norm epilogue.
// ---------------------------------------------------------------------------
__global__ __launch_bounds__(256) void mma_gemm_qk_norm(
    const __nv_bfloat16* __restrict__ Agh, const __nv_bfloat16* __restrict__ Bgh,
    const float* __restrict__ bias2, const float* __restrict__ scale_ptr,
    __nv_bfloat16* __restrict__ Qh, __nv_bfloat16* __restrict__ Kh, int K)
{
    extern __shared__ __nv_bfloat16 S[];
    __shared__ float sp[128][5];

    int tid  = threadIdx.x;
    int lane = tid & 31;
    int w    = tid >> 5;
    int wm   = (w >> 2) * 64;
    int wc   = w & 3;
    int wn   = wc * 32;
    int bm   = blockIdx.y * GBM;
    int bn   = blockIdx.x * GBN;
    int g    = lane >> 2;
    int cp   = (lane & 3) * 2;

    int lA_r = lane & 15;
    int lA_c = (lane >> 4) << 3;
    int lB_r = ((lane >> 4) << 3) + (lane & 7);
    int lB_c = ((lane >> 3) & 1) << 3;

    auto load_tile = [&](int t, int st) {
        int k0 = t * GBK;
        #pragma unroll
        for (int a = 0; a < 2; a++) {
            const __nv_bfloat16* gsrc = (a == 0) ? Agh : Bgh;
            int rowbase = (a == 0) ? bm : bn;
            __nv_bfloat16* dst = S + (st * 2 + a) * GTSZ;
            #pragma unroll
            for (int u = 0; u < 2; u++) {
                int idx = tid + u * 256;
                int r   = idx >> 2;
                int c8  = (idx & 3) * 8;
                cp_async16(dst + r * GP + c8, gsrc + (size_t)(rowbase + r) * K + k0 + c8);
            }
        }
    };

    float acc[4][4][4];
    #pragma unroll
    for (int i = 0; i < 4; i++)
        #pragma unroll
        for (int j = 0; j < 4; j++)
            #pragma unroll
            for (int q = 0; q < 4; q++) acc[i][j][q] = 0.f;

    int nk = K / GBK;
    load_tile(0, 0);
    CP_COMMIT();

    for (int t = 0; t < nk; t++) {
        int st = t & 1;
        if (t + 1 < nk) { load_tile(t + 1, st ^ 1); CP_COMMIT(); CP_WAIT(1); }
        else            { CP_WAIT(0); }
        __syncthreads();

        const __nv_bfloat16* Ah = S + (st * 2 + 0) * GTSZ;
        const __nv_bfloat16* Bh = S + (st * 2 + 1) * GTSZ;

        #pragma unroll
        for (int ks = 0; ks < 2; ks++) {
            int k16 = ks * 16;
            uint32_t bh[4][2];
            #pragma unroll
            for (int np = 0; np < 2; np++) {
                int nbase = wn + np * 16;
                ldsm_x4(bh[2*np][0], bh[2*np][1], bh[2*np+1][0], bh[2*np+1][1],
                        &Bh[(nbase + lB_r) * GP + k16 + lB_c]);
            }
            #pragma unroll
            for (int mt = 0; mt < 4; mt++) {
                int r = wm + mt * 16;
                uint32_t ah0, ah1, ah2, ah3;
                ldsm_x4(ah0, ah1, ah2, ah3, &Ah[(r + lA_r) * GP + k16 + lA_c]);
                #pragma unroll
                for (int nt = 0; nt < 4; nt++)
                    mma_bf16(acc[mt][nt], ah0, ah1, ah2, ah3, bh[nt][0], bh[nt][1]);
            }
        }
        __syncthreads();
    }

    #pragma unroll
    for (int mt = 0; mt < 4; mt++) {
        #pragma unroll
        for (int nt = 0; nt < 4; nt++) {
            int col = bn + wn + nt * 8 + cp;
            float b0 = bias2[col], b1 = bias2[col + 1];
            acc[mt][nt][0] += b0; acc[mt][nt][1] += b1;
            acc[mt][nt][2] += b0; acc[mt][nt][3] += b1;
        }
    }
    #pragma unroll
    for (int mt = 0; mt < 4; mt++) {
        float p0 = 0.f, p1 = 0.f;
        #pragma unroll
        for (int nt = 0; nt < 4; nt++) {
            p0 += acc[mt][nt][0] * acc[mt][nt][0] + acc[mt][nt][1] * acc[mt][nt][1];
            p1 += acc[mt][nt][2] * acc[mt][nt][2] + acc[mt][nt][3] * acc[mt][nt][3];
        }
        p0 += __shfl_xor_sync(0xffffffffu, p0, 1, 4);
        p0 += __shfl_xor_sync(0xffffffffu, p0, 2, 4);
        p1 += __shfl_xor_sync(0xffffffffu, p1, 1, 4);
        p1 += __shfl_xor_sync(0xffffffffu, p1, 2, 4);
        if ((lane & 3) == 0) {
            sp[wm + mt * 16 + g][wc]     = p0;
            sp[wm + mt * 16 + g + 8][wc] = p1;
        }
    }
    __syncthreads();

    float qscale = *scale_ptr;
    int hd2 = (wc >> 1) << 1;
    #pragma unroll
    for (int mt = 0; mt < 4; mt++) {
        int r0 = wm + mt * 16 + g;
        int r1 = r0 + 8;
        float n0 = sp[r0][hd2] + sp[r0][hd2 + 1];
        float n1 = sp[r1][hd2] + sp[r1][hd2 + 1];
        float i0 = qscale / fmaxf(sqrtf(n0), 1e-12f);
        float i1 = qscale / fmaxf(sqrtf(n1), 1e-12f);
        #pragma unroll
        for (int nt = 0; nt < 4; nt++) {
            int colg = bn + wn + nt * 8 + cp;
            __nv_bfloat16* outp = (colg < 1024) ? Qh : Kh;
            int colq = colg & 1023;
            uint32_t v0 = packbf(acc[mt][nt][0] * i0, acc[mt][nt][1] * i0);
            uint32_t v1 = packbf(acc[mt][nt][2] * i1, acc[mt][nt][3] * i1);
            *reinterpret_cast<uint32_t*>(outp + (size_t)(bm + r0) * Esz + colq) = v0;
            *reinterpret_cast<uint32_t*>(outp + (size_t)(bm + r1) * Esz + colq) = v1;
        }
    }
}

// ---------------------------------------------------------------------------
// V transpose per head (reads compact vf [tok][1024]): vth, pvs, ts.
// ---------------------------------------------------------------------------
__global__ void vtrans_kernel(const float* __restrict__ vf,
                              __nv_bfloat16* __restrict__ vth,
                              float* __restrict__ ts,
                              float* __restrict__ pvs)
{
    __shared__ float sv[64][65];
    int kt = blockIdx.x;
    int bh = blockIdx.y;
    int b  = bh >> 4;
    int h  = bh & 15;
    int s0 = kt * 64;
    int tid = threadIdx.x;

    const float* Vb = vf + ((size_t)(b * Ssz + s0)) * Esz + h * Dsz;
    #pragma unroll
    for (int u = 0; u < 4; u++) {
        int idx = tid + u * 256;
        int r   = idx >> 4;
        int c4  = (idx & 15) * 4;
        float4 v = *reinterpret_cast<const float4*>(Vb + (size_t)r * Esz + c4);
        sv[c4 + 0][r] = v.x;
        sv[c4 + 1][r] = v.y;
        sv[c4 + 2][r] = v.z;
        sv[c4 + 3][r] = v.w;
    }
    __syncthreads();

    size_t base = ((size_t)bh * Dsz) * Ssz + s0;
    #pragma unroll
    for (int u = 0; u < 4; u++) {
        int idx = tid + u * 256;
        int d   = idx >> 4;
        int s4  = (idx & 15) * 4;
        uint32_t h0 = packbf(sv[d][s4],     sv[d][s4 + 1]);
        uint32_t h1 = packbf(sv[d][s4 + 2], sv[d][s4 + 3]);
        *reinterpret_cast<uint2*>(vth + base + (size_t)d * Ssz + s4) = make_uint2(h0, h1);
    }
    __syncthreads();

    if (tid < 64) {
        float acc = 0.f;
        #pragma unroll
        for (int r = 0; r < 64; r++) { acc += sv[tid][r]; sv[tid][r] = acc; }
        ts[((size_t)bh * NKT + kt) * Dsz + tid] = acc;
    }
    __syncthreads();

    size_t pbase = ((size_t)bh * Ssz + s0) * Dsz;
    #pragma unroll
    for (int u = 0; u < 4; u++) {
        int idx = tid + u * 256;
        int r   = idx >> 4;
        int c4  = (idx & 15) * 4;
        float4 f;
        f.x = sv[c4 + 0][r]; f.y = sv[c4 + 1][r];
        f.z = sv[c4 + 2][r]; f.w = sv[c4 + 3][r];
        *reinterpret_cast<float4*>(pvs + pbase + (size_t)r * Dsz + c4) = f;
    }
}

// ---------------------------------------------------------------------------
// Exclusive prefix over tile sums
// ---------------------------------------------------------------------------
__global__ void ts_prefix_kernel(const float* __restrict__ ts,
                                 float* __restrict__ epts)
{
    int bh = blockIdx.x;
    int d  = threadIdx.x;
    float acc = 0.f;
    for (int kt = 0; kt < NKT; kt++) {
        epts[((size_t)bh * NKT + kt) * Dsz + d] = acc;
        acc += ts[((size_t)bh * NKT + kt) * Dsz + d];
    }
}

// ---------------------------------------------------------------------------
// Flash attention via uniform-softmax decomposition (round-11 notes).
// ---------------------------------------------------------------------------
#define AP 72
#define ATSZ (64 * AP)
#define ATTN_SMEM (2 * 2 * ATSZ * 2)

__global__ __launch_bounds__(256) void attn_mma_kernel(
    const __nv_bfloat16* __restrict__ Qh, const __nv_bfloat16* __restrict__ Kh,
    const __nv_bfloat16* __restrict__ Vth,
    const float* __restrict__ epts, const float* __restrict__ pvs,
    __nv_bfloat16* __restrict__ Oh, __nv_bfloat16* __restrict__ Ol)
{
    extern __shared__ __nv_bfloat16 SA[];

    int bh = blockIdx.y;
    int b  = bh >> 4;
    int h  = bh & 15;
    int qt = (gridDim.x - 1) - blockIdx.x;

    int tid  = threadIdx.x;
    int lane = tid & 31;
    int w    = tid >> 5;
    int g    = lane >> 2;
    int cp   = (lane & 3) * 2;

    int lB_r = ((lane >> 4) << 3) + (lane & 7);
    int lB_c = ((lane >> 3) & 1) << 3;

    int qrow0 = qt * 128 + w * 16;
    int row0  = qrow0 + g;
    int row1  = row0 + 8;
    int wmax  = qrow0 + 15;

    const __nv_bfloat16* Kb  = Kh  + ((size_t)b * Ssz) * Esz + h * Dsz;
    const __nv_bfloat16* Vbh = Vth + ((size_t)bh * Dsz) * Ssz;

    auto load_tile = [&](int kt, int st) {
        int kbase = kt * 64;
        __nv_bfloat16* Ks = SA + st * 2 * ATSZ;
        __nv_bfloat16* Vh = Ks + ATSZ;
        #pragma unroll
        for (int u = 0; u < 4; u++) {
            int idx  = tid + u * 256;
            int a    = idx >> 9;
            int idx2 = idx & 511;
            int rr   = idx2 >> 3;
            int c8   = (idx2 & 7) * 8;
            if (a == 0)
                cp_async16(Ks + rr * AP + c8, Kb + (size_t)(kbase + rr) * Esz + c8);
            else
                cp_async16(Vh + rr * AP + c8, Vbh + (size_t)rr * Ssz + kbase + c8);
        }
    };

    uint32_t aQ[4][4];
    const __nv_bfloat16* Qb = Qh + ((size_t)(b * Ssz + qrow0)) * Esz + h * Dsz;
    #pragma unroll
    for (int ks = 0; ks < 4; ks++) {
        int c = ks * 16 + cp;
        aQ[ks][0] = *reinterpret_cast<const uint32_t*>(Qb + (size_t)g * Esz + c);
        aQ[ks][1] = *reinterpret_cast<const uint32_t*>(Qb + (size_t)(g + 8) * Esz + c);
        aQ[ks][2] = *reinterpret_cast<const uint32_t*>(Qb + (size_t)g * Esz + c + 8);
        aQ[ks][3] = *reinterpret_cast<const uint32_t*>(Qb + (size_t)(g + 8) * Esz + c + 8);
    }

    float o[8][4];
    #pragma unroll
    for (int i = 0; i < 8; i++)
        #pragma unroll
        for (int j = 0; j < 4; j++) o[i][j] = 0.f;
    float l0 = 0.f, l1 = 0.f;

    int ktmax = qt * 2 + 1;
    load_tile(0, 0);
    CP_COMMIT();

    for (int kt = 0; kt <= ktmax; kt++) {
        int st = kt & 1;
        if (kt + 1 <= ktmax) { load_tile(kt + 1, st ^ 1); CP_COMMIT(); CP_WAIT(1); }
        else                 { CP_WAIT(0); }
        __syncthreads();

        int kbase = kt * 64;
        if (kbase <= wmax) {
            const __nv_bfloat16* Ks = SA + st * 2 * ATSZ;
            const __nv_bfloat16* Vh = Ks + ATSZ;

            float sc[8][4];
            #pragma unroll
            for (int nt = 0; nt < 8; nt++)
                #pragma unroll
                for (int j = 0; j < 4; j++) sc[nt][j] = 0.f;
            #pragma unroll
            for (int ks = 0; ks < 4; ks++) {
                int k16 = ks * 16;
                uint32_t bk[8][2];
                #pragma unroll
                for (int np = 0; np < 4; np++)
                    ldsm_x4(bk[2*np][0], bk[2*np][1], bk[2*np+1][0], bk[2*np+1][1],
                            &Ks[(np * 16 + lB_r) * AP + k16 + lB_c]);
                #pragma unroll
                for (int nt = 0; nt < 8; nt++)
                    mma_bf16(sc[nt], aQ[ks][0], aQ[ks][1], aQ[ks][2], aQ[ks][3],
                             bk[nt][0], bk[nt][1]);
            }

            float ps0 = 0.f, ps1 = 0.f;
            #pragma unroll
            for (int nt = 0; nt < 8; nt++) {
                int c0 = kbase + nt * 8 + cp;
                float x0 = sc[nt][0], x1 = sc[nt][1], x2 = sc[nt][2], x3 = sc[nt][3];
                float d0 = x0 * (1.f + x0 * (0.5f + x0 * (1.f / 6.f)));
                float d1 = x1 * (1.f + x1 * (0.5f + x1 * (1.f / 6.f)));
                float d2 = x2 * (1.f + x2 * (0.5f + x2 * (1.f / 6.f)));
                float d3 = x3 * (1.f + x3 * (0.5f + x3 * (1.f / 6.f)));
                if (c0     > row0) d0 = 0.f;
                if (c0 + 1 > row0) d1 = 0.f;
                if (c0     > row1) d2 = 0.f;
                if (c0 + 1 > row1) d3 = 0.f;
                sc[nt][0] = d0; sc[nt][1] = d1; sc[nt][2] = d2; sc[nt][3] = d3;
                ps0 += d0 + d1;
                ps1 += d2 + d3;
            }
            l0 += ps0; l1 += ps1;

            uint32_t aP[4][4];
            #pragma unroll
            for (int kk = 0; kk < 4; kk++) {
                aP[kk][0] = packbf(sc[2*kk][0],   sc[2*kk][1]);
                aP[kk][1] = packbf(sc[2*kk][2],   sc[2*kk][3]);
                aP[kk][2] = packbf(sc[2*kk+1][0], sc[2*kk+1][1]);
                aP[kk][3] = packbf(sc[2*kk+1][2], sc[2*kk+1][3]);
            }

            #pragma unroll
            for (int kk = 0; kk < 4; kk++) {
                int k16 = kk * 16;
                uint32_t bv[8][2];
                #pragma unroll
                for (int np = 0; np < 4; np++)
                    ldsm_x4(bv[2*np][0], bv[2*np][1], bv[2*np+1][0], bv[2*np+1][1],
                            &Vh[(np * 16 + lB_r) * AP + k16 + lB_c]);
                #pragma unroll
                for (int dt = 0; dt < 8; dt++)
                    mma_bf16(o[dt], aP[kk][0], aP[kk][1], aP[kk][2], aP[kk][3],
                             bv[dt][0], bv[dt][1]);
            }
        }
        __syncthreads();
    }

    l0 += __shfl_xor_sync(0xffffffffu, l0, 1, 4);
    l0 += __shfl_xor_sync(0xffffffffu, l0, 2, 4);
    l1 += __shfl_xor_sync(0xffffffffu, l1, 1, 4);
    l1 += __shfl_xor_sync(0xffffffffu, l1, 2, 4);
    float i0 = 1.0f / ((float)(row0 + 1) + l0);
    float i1 = 1.0f / ((float)(row1 + 1) + l1);

    const float* ep0 = epts + ((size_t)bh * NKT + (row0 >> 6)) * Dsz;
    const float* ep1 = epts + ((size_t)bh * NKT + (row1 >> 6)) * Dsz;
    const float* pv0 = pvs + ((size_t)bh * Ssz + row0) * Dsz;
    const float* pv1 = pvs + ((size_t)bh * Ssz + row1) * Dsz;

    __nv_bfloat16* Ohb = Oh + ((size_t)(b * Ssz + qrow0)) * Esz + h * Dsz;
    __nv_bfloat16* Olb = Ol + ((size_t)(b * Ssz + qrow0)) * Esz + h * Dsz;
    #pragma unroll
    for (int dt = 0; dt < 8; dt++) {
        int c = dt * 8 + cp;
        float a0 = ep0[c]     + pv0[c];
        float a1 = ep0[c + 1] + pv0[c + 1];
        float b0 = ep1[c]     + pv1[c];
        float b1 = ep1[c + 1] + pv1[c + 1];
        uint32_t h0, lo0, h1, lo1;
        split2((o[dt][0] + a0) * i0, (o[dt][1] + a1) * i0, h0, lo0);
        split2((o[dt][2] + b0) * i1, (o[dt][3] + b1) * i1, h1, lo1);
        *reinterpret_cast<uint32_t*>(Ohb + (size_t)g * Esz + c)       = h0;
        *reinterpret_cast<uint32_t*>(Olb + (size_t)g * Esz + c)       = lo0;
        *reinterpret_cast<uint32_t*>(Ohb + (size_t)(g + 8) * Esz + c) = h1;
        *reinterpret_cast<uint32_t*>(Olb + (size_t)(g + 8) * Esz + c) = lo1;
    }
}

// ---------------------------------------------------------------------------
extern "C" void kernel_launch(void* const* d_in, const int* in_sizes, int n_in,
                              void* d_out, int out_size)
{
    const float* x       = (const float*)d_in[0];
    const float* ln_w    = (const float*)d_in[1];
    const float* ln_b    = (const float*)d_in[2];
    const float* qkv_w   = (const float*)d_in[3];
    const float* qkv_b   = (const float*)d_in[4];
    const float* qk_scal = (const float*)d_in[5];
    const float* out_w   = (const float*)d_in[6];
    const float* out_b   = (const float*)d_in[7];
    const float* invfreq = (const float*)d_in[8];
    float* out = (float*)d_out;

    float *vf, *ts, *epts, *pvs, *qb2;
    cudaGetSymbolAddress((void**)&vf,   g_vf);
    cudaGetSymbolAddress((void**)&ts,   g_ts);
    cudaGetSymbolAddress((void**)&epts, g_epts);
    cudaGetSymbolAddress((void**)&pvs,  g_pvs);
    cudaGetSymbolAddress((void**)&qb2,  g_qb2);
    __nv_bfloat16 *xnh, *xnl, *wqh, *wql, *woh, *wol, *qh, *kh, *vth, *ath, *atl;
    cudaGetSymbolAddress((void**)&xnh, g_xnh);
    cudaGetSymbolAddress((void**)&xnl, g_xnl);
    cudaGetSymbolAddress((void**)&wqh, g_wqh);
    cudaGetSymbolAddress((void**)&wql, g_wql);
    cudaGetSymbolAddress((void**)&woh, g_woh);
    cudaGetSymbolAddress((void**)&wol, g_wol);
    cudaGetSymbolAddress((void**)&qh,  g_qh);
    cudaGetSymbolAddress((void**)&kh,  g_kh);
    cudaGetSymbolAddress((void**)&vth, g_vth);
    cudaGetSymbolAddress((void**)&ath, g_ath);
    cudaGetSymbolAddress((void**)&atl, g_atl);

    cudaFuncSetAttribute(mma_gemm_split3,
                         cudaFuncAttributeMaxDynamicSharedMemorySize, GEMM_SMEM3);
    cudaFuncSetAttribute(mma_gemm_qk_norm,
                         cudaFuncAttributeMaxDynamicSharedMemorySize, GEMM_SMEM1);
    cudaFuncSetAttribute(attn_mma_kernel,
                         cudaFuncAttributeMaxDynamicSharedMemorySize, ATTN_SMEM);

    static cudaStream_t s1 = nullptr, s2 = nullptr;
    static cudaEvent_t evStart = nullptr, evLN = nullptr, evRotW = nullptr,
                       evSide1 = nullptr, evSide2 = nullptr;
    if (s1 == nullptr) {
        cudaStreamCreateWithFlags(&s1, cudaStreamNonBlocking);
        cudaStreamCreateWithFlags(&s2, cudaStreamNonBlocking);
        cudaEventCreateWithFlags(&evStart, cudaEventDisableTiming);
        cudaEventCreateWithFlags(&evLN,    cudaEventDisableTiming);
        cudaEventCreateWithFlags(&evRotW,  cudaEventDisableTiming);
        cudaEventCreateWithFlags(&evSide1, cudaEventDisableTiming);
        cudaEventCreateWithFlags(&evSide2, cudaEventDisableTiming);
    }
    cudaStream_t s0 = 0;

    // fork
    cudaEventRecord(evStart, s0);
    cudaStreamWaitEvent(s1, evStart, 0);
    cudaStreamWaitEvent(s2, evStart, 0);

    // s2: sincos -> rotation-folded QK weights + bias -> out_w split
    sincos_kernel<<<4, 256, 0, s2>>>(invfreq);
    cvt_rot_kernel<<<2048 * 256 / 256, 256, 0, s2>>>(qkv_w, wqh);
    rotbias_kernel<<<8, 256, 0, s2>>>(qkv_b, qb2);
    cudaEventRecord(evRotW, s2);
    cvt_split_kernel<<<(Esz * Esz / 4 + 255) / 256, 256, 0, s2>>>(out_w, woh, wol, Esz * Esz / 4);
    cudaEventRecord(evSide2, s2);

    // s1: V-weight split, then (after ln) V-GEMM -> vtrans -> ts_prefix
    cvt_split_kernel<<<(1024 * Esz / 4 + 255) / 256, 256, 0, s1>>>(
        qkv_w + (size_t)2048 * Esz, wqh + (size_t)2048 * Esz, wql + (size_t)2048 * Esz,
        1024 * Esz / 4);

    // s0: LN
    ln_kernel<<<TOK, 256, 0, s0>>>(x, ln_w, ln_b, xnh, xnl);
    cudaEventRecord(evLN, s0);

    // s1 continues after LN
    cudaStreamWaitEvent(s1, evLN, 0);
    mma_gemm_split3<<<dim3(1024 / GBN, TOK / GBM), 256, GEMM_SMEM3, s1>>>(
        xnh, xnl, wqh + (size_t)2048 * Esz, wql + (size_t)2048 * Esz,
        qkv_b + 2048, vf, Esz, Esz);
    vtrans_kernel<<<dim3(NKT, Bsz * Hsz), 256, 0, s1>>>(vf, vth, ts, pvs);
    ts_prefix_kernel<<<Bsz * Hsz, Dsz, 0, s1>>>(ts, epts);
    cudaEventRecord(evSide1, s1);

    // s0: QK GEMM with fused rotation (in weights) + per-head L2 norm
    cudaStreamWaitEvent(s0, evRotW, 0);
    mma_gemm_qk_norm<<<dim3(2048 / GBN, TOK / GBM), 256, GEMM_SMEM1, s0>>>(
        xnh, wqh, qb2, qk_scal, qh, kh, Esz);

    // join, attention + output GEMM
    cudaStreamWaitEvent(s0, evSide1, 0);
    attn_mma_kernel<<<dim3(Ssz / 128, Bsz * Hsz), 256, ATTN_SMEM, s0>>>(
        qh, kh, vth, epts, pvs, ath, atl);
    cudaStreamWaitEvent(s0, evSide2, 0);
    mma_gemm_split3<<<dim3(Esz / GBN, TOK / GBM), 256, GEMM_SMEM3, s0>>>(
        ath, atl, woh, wol, out_b, out, Esz, Esz);
}